// round 11
// baseline (speedup 1.0000x reference)
#include <cuda_runtime.h>
#include <math.h>

// Problem constants
#define NN   50000
#define DD   128
#define MM   800000
#define EE   32
#define KIN  160    // D + E
#define MSGD 128

// Edge kernel tiling: 64 edges/block, 256 threads, per-thread 4 rows x 8 cols
#define TE   64
#define EIS  164    // padded: 4*164 mod 32 != 0 -> no LDS bank conflict
#define HS   260    // padded likewise

// GRU kernel tiling
#define TN   32
#define XS   128
#define GS   384

typedef unsigned long long u64;

// Scratch (allocation-free rule: __device__ globals)
__device__ float g_msgsum[(size_t)NN * DD];
__device__ float g_bufA[(size_t)NN * DD];
__device__ float g_bufB[(size_t)NN * DD];

__device__ __forceinline__ float sigf(float x) { return 1.0f / (1.0f + expf(-x)); }

// ---- packed f32x2 helpers (bit-identical to 2x scalar FFMA) ----
__device__ __forceinline__ u64 pack2(float x) {
    u64 r;
    asm("mov.b64 %0, {%1, %1};" : "=l"(r) : "r"(__float_as_uint(x)));
    return r;
}
__device__ __forceinline__ void ffma2(u64& d, u64 a, u64 b) {
    asm("fma.rn.f32x2 %0, %1, %2, %0;" : "+l"(d) : "l"(a), "l"(b));
}
__device__ __forceinline__ void unpack2(u64 v, float& lo, float& hi) {
    unsigned int a, b;
    asm("mov.b64 {%0, %1}, %2;" : "=r"(a), "=r"(b) : "l"(v));
    lo = __uint_as_float(a); hi = __uint_as_float(b);
}

// ---------------------------------------------------------------------------
__global__ void copy_relu_kernel(const float* __restrict__ src, float* __restrict__ dst,
                                 int n, int do_relu) {
    int i = blockIdx.x * blockDim.x + threadIdx.x;
    if (i < n) {
        float v = src[i];
        dst[i] = do_relu ? fmaxf(v, 0.0f) : v;
    }
}

// ---------------------------------------------------------------------------
// Fused edge kernel. 64 edges/block, 256 threads.
// Thread tile: 4 rows (rg = tid>>4, rb = rg*4) x 8 cols (cg = tid&15, cb = cg*8).
// Weight LDG.128s are lane-distinct across 16 colgroups (L1-resident reuse);
// edge/hidden values come from broadcast LDS. Single-k weight prefetch.
// 108.5KB smem -> 2 blocks/SM = 16 warps (occ 25%).
// ---------------------------------------------------------------------------
__global__ void __launch_bounds__(256, 2)
edge_kernel(const float* __restrict__ state,
            const int*   __restrict__ eidx,
            const float* __restrict__ efeat,
            const float* __restrict__ W1p, const float* __restrict__ b1p,
            const float* __restrict__ W2p, const float* __restrict__ b2p,
            const float* __restrict__ A1p, const float* __restrict__ ab1p,
            const float* __restrict__ A2p, const float* __restrict__ ab2p,
            float* __restrict__ msum)
{
    extern __shared__ float sm[];
    float* s_ei = sm;              // TE * EIS  (reused as gate buffer later)
    float* s_h  = sm + TE * EIS;   // TE * HS
    __shared__ int s_src[TE];
    __shared__ int s_dst[TE];

    const int tid = threadIdx.x;
    const int m0  = blockIdx.x * TE;

    if (tid < TE) {
        s_src[tid] = eidx[m0 + tid];
        s_dst[tid] = eidx[MM + m0 + tid];
    }
    __syncthreads();

    // Gather diff part: 64 edges x 32 float4
    for (int t = tid; t < TE * 32; t += 256) {
        int e = t >> 5, q = t & 31;
        const float4 a = ((const float4*)(state + (size_t)s_src[e] * DD))[q];
        const float4 b = ((const float4*)(state + (size_t)s_dst[e] * DD))[q];
        float4 v; v.x = a.x - b.x; v.y = a.y - b.y; v.z = a.z - b.z; v.w = a.w - b.w;
        *(float4*)(s_ei + e * EIS + q * 4) = v;
    }
    // Edge features: 64 edges x 8 float4
    for (int t = tid; t < TE * 8; t += 256) {
        int e = t >> 3, q = t & 7;
        float4 v = ((const float4*)(efeat + (size_t)(m0 + e) * EE))[q];
        *(float4*)(s_ei + e * EIS + DD + q * 4) = v;
    }
    __syncthreads();

    const int cg = tid & 15;     // 16 col groups x 8 cols = 128 cols
    const int rg = tid >> 4;     // 16 row groups x 4 rows = 64 rows
    const int cb = cg * 8;
    const int rb = rg * 4;

    // ---- GEMM1: H = relu(EI @ W + b), halves: 0 = msg net (W1), 1 = att net (A1)
    #pragma unroll
    for (int half = 0; half < 2; half++) {
        const float* Wp = half ? A1p : W1p;
        const float* bp = half ? ab1p : b1p;
        u64 acc[4][4];
        #pragma unroll
        for (int r = 0; r < 4; r++)
            #pragma unroll
            for (int c = 0; c < 4; c++) acc[r][c] = 0ull;

        ulonglong2 wa = *(const ulonglong2*)(Wp + cb);
        ulonglong2 wb = *(const ulonglong2*)(Wp + cb + 4);
        for (int k = 0; k < KIN; k++) {
            int kn = (k + 1 < KIN) ? (k + 1) : 0;
            ulonglong2 na = *(const ulonglong2*)(Wp + kn * MSGD + cb);
            ulonglong2 nb = *(const ulonglong2*)(Wp + kn * MSGD + cb + 4);
            #pragma unroll
            for (int r = 0; r < 4; r++) {
                u64 ev = pack2(s_ei[(rb + r) * EIS + k]);
                ffma2(acc[r][0], ev, wa.x);
                ffma2(acc[r][1], ev, wa.y);
                ffma2(acc[r][2], ev, wb.x);
                ffma2(acc[r][3], ev, wb.y);
            }
            wa = na; wb = nb;
        }
        const float4 blo = *(const float4*)(bp + cb);
        const float4 bhi = *(const float4*)(bp + cb + 4);
        #pragma unroll
        for (int r = 0; r < 4; r++) {
            float v0, v1, v2, v3, v4, v5, v6, v7;
            unpack2(acc[r][0], v0, v1);
            unpack2(acc[r][1], v2, v3);
            unpack2(acc[r][2], v4, v5);
            unpack2(acc[r][3], v6, v7);
            float4 o0, o1;
            o0.x = fmaxf(v0 + blo.x, 0.f); o0.y = fmaxf(v1 + blo.y, 0.f);
            o0.z = fmaxf(v2 + blo.z, 0.f); o0.w = fmaxf(v3 + blo.w, 0.f);
            o1.x = fmaxf(v4 + bhi.x, 0.f); o1.y = fmaxf(v5 + bhi.y, 0.f);
            o1.z = fmaxf(v6 + bhi.z, 0.f); o1.w = fmaxf(v7 + bhi.w, 0.f);
            *(float4*)(s_h + (rb + r) * HS + half * MSGD + cb)     = o0;
            *(float4*)(s_h + (rb + r) * HS + half * MSGD + cb + 4) = o1;
        }
    }
    __syncthreads();
    // s_ei is dead now; reuse as per-thread gate buffer.

    // ---- GEMM2a: att = HA @ A2 + ab2 -> gate = sigmoid, staged in s_ei ----
    {
        u64 acc[4][4];
        #pragma unroll
        for (int r = 0; r < 4; r++)
            #pragma unroll
            for (int c = 0; c < 4; c++) acc[r][c] = 0ull;

        ulonglong2 wa = *(const ulonglong2*)(A2p + cb);
        ulonglong2 wb = *(const ulonglong2*)(A2p + cb + 4);
        for (int k = 0; k < MSGD; k++) {
            int kn = (k + 1 < MSGD) ? (k + 1) : 0;
            ulonglong2 na = *(const ulonglong2*)(A2p + kn * MSGD + cb);
            ulonglong2 nb = *(const ulonglong2*)(A2p + kn * MSGD + cb + 4);
            #pragma unroll
            for (int r = 0; r < 4; r++) {
                u64 hv = pack2(s_h[(rb + r) * HS + MSGD + k]);
                ffma2(acc[r][0], hv, wa.x);
                ffma2(acc[r][1], hv, wa.y);
                ffma2(acc[r][2], hv, wb.x);
                ffma2(acc[r][3], hv, wb.y);
            }
            wa = na; wb = nb;
        }
        const float4 alo = *(const float4*)(ab2p + cb);
        const float4 ahi = *(const float4*)(ab2p + cb + 4);
        #pragma unroll
        for (int r = 0; r < 4; r++) {
            float a0, a1, a2, a3, a4, a5, a6, a7;
            unpack2(acc[r][0], a0, a1);
            unpack2(acc[r][1], a2, a3);
            unpack2(acc[r][2], a4, a5);
            unpack2(acc[r][3], a6, a7);
            float4 g0, g1;
            g0.x = sigf(a0 + alo.x); g0.y = sigf(a1 + alo.y);
            g0.z = sigf(a2 + alo.z); g0.w = sigf(a3 + alo.w);
            g1.x = sigf(a4 + ahi.x); g1.y = sigf(a5 + ahi.y);
            g1.z = sigf(a6 + ahi.z); g1.w = sigf(a7 + ahi.w);
            *(float4*)(s_ei + (rb + r) * EIS + cb)     = g0;
            *(float4*)(s_ei + (rb + r) * EIS + cb + 4) = g1;
        }
    }

    // ---- GEMM2b: msg = H1 @ W2 + b2; scatter msg*gate into msum ----
    {
        u64 acc[4][4];
        #pragma unroll
        for (int r = 0; r < 4; r++)
            #pragma unroll
            for (int c = 0; c < 4; c++) acc[r][c] = 0ull;

        ulonglong2 wa = *(const ulonglong2*)(W2p + cb);
        ulonglong2 wb = *(const ulonglong2*)(W2p + cb + 4);
        for (int k = 0; k < MSGD; k++) {
            int kn = (k + 1 < MSGD) ? (k + 1) : 0;
            ulonglong2 na = *(const ulonglong2*)(W2p + kn * MSGD + cb);
            ulonglong2 nb = *(const ulonglong2*)(W2p + kn * MSGD + cb + 4);
            #pragma unroll
            for (int r = 0; r < 4; r++) {
                u64 hv = pack2(s_h[(rb + r) * HS + k]);
                ffma2(acc[r][0], hv, wa.x);
                ffma2(acc[r][1], hv, wa.y);
                ffma2(acc[r][2], hv, wb.x);
                ffma2(acc[r][3], hv, wb.y);
            }
            wa = na; wb = nb;
        }
        const float4 blo = *(const float4*)(b2p + cb);
        const float4 bhi = *(const float4*)(b2p + cb + 4);
        #pragma unroll
        for (int r = 0; r < 4; r++) {
            float m0v, m1v, m2v, m3v, m4v, m5v, m6v, m7v;
            unpack2(acc[r][0], m0v, m1v);
            unpack2(acc[r][1], m2v, m3v);
            unpack2(acc[r][2], m4v, m5v);
            unpack2(acc[r][3], m6v, m7v);
            float4 g0 = *(const float4*)(s_ei + (rb + r) * EIS + cb);
            float4 g1 = *(const float4*)(s_ei + (rb + r) * EIS + cb + 4);
            float* dp = msum + (size_t)s_dst[rb + r] * DD + cb;
            atomicAdd(dp + 0, (m0v + blo.x) * g0.x);
            atomicAdd(dp + 1, (m1v + blo.y) * g0.y);
            atomicAdd(dp + 2, (m2v + blo.z) * g0.z);
            atomicAdd(dp + 3, (m3v + blo.w) * g0.w);
            atomicAdd(dp + 4, (m4v + bhi.x) * g1.x);
            atomicAdd(dp + 5, (m5v + bhi.y) * g1.y);
            atomicAdd(dp + 6, (m6v + bhi.z) * g1.z);
            atomicAdd(dp + 7, (m7v + bhi.w) * g1.w);
        }
    }
}

// ---------------------------------------------------------------------------
// Fused GRU kernel: per 32-node tile, 256 threads, f32x2 + weight prefetch.
// ---------------------------------------------------------------------------
__global__ void __launch_bounds__(256)
gru_kernel(const float* __restrict__ xmsg, const float* __restrict__ hstate,
           const float* __restrict__ Wih, const float* __restrict__ bih,
           const float* __restrict__ Whh, const float* __restrict__ bhh,
           float* __restrict__ out)
{
    extern __shared__ float sm[];
    float* s_x  = sm;                        // TN * XS
    float* s_h  = s_x + TN * XS;             // TN * XS
    float* s_gi = s_h + TN * XS;             // TN * GS
    float* s_gh = s_gi + TN * GS;            // TN * GS

    const int tid = threadIdx.x;
    const int n0  = blockIdx.x * TN;

    for (int t = tid; t < TN * 32; t += 256) {
        int r = t >> 5, q = t & 31;
        int node = n0 + r;
        float4 vx = make_float4(0.f, 0.f, 0.f, 0.f);
        float4 vh = vx;
        if (node < NN) {
            vx = ((const float4*)(xmsg   + (size_t)node * DD))[q];
            vh = ((const float4*)(hstate + (size_t)node * DD))[q];
        }
        *(float4*)(s_x + r * XS + q * 4) = vx;
        *(float4*)(s_h + r * XS + q * 4) = vh;
    }
    __syncthreads();

    const int lane = tid & 31;
    const int wg   = tid >> 5;     // 8 row groups
    const int rb   = wg * 4;
    const int cb   = lane * 12;    // 32*12 = 384 cols

    #pragma unroll
    for (int pass = 0; pass < 2; pass++) {
        const float* xs = pass ? s_h : s_x;
        const float* Wp = pass ? Whh : Wih;
        const float* bp = pass ? bhh : bih;
        float* gout     = pass ? s_gh : s_gi;

        u64 acc[4][6];
        #pragma unroll
        for (int i = 0; i < 4; i++)
            #pragma unroll
            for (int j = 0; j < 6; j++) acc[i][j] = 0ull;

        ulonglong2 w0a = *(const ulonglong2*)(Wp + 0 * 384 + cb);
        ulonglong2 w1a = *(const ulonglong2*)(Wp + 0 * 384 + cb + 4);
        ulonglong2 w2a = *(const ulonglong2*)(Wp + 0 * 384 + cb + 8);
        for (int k = 0; k < DD; k++) {
            int kn = (k + 1 < DD) ? (k + 1) : 0;
            ulonglong2 w0b = *(const ulonglong2*)(Wp + kn * 384 + cb);
            ulonglong2 w1b = *(const ulonglong2*)(Wp + kn * 384 + cb + 4);
            ulonglong2 w2b = *(const ulonglong2*)(Wp + kn * 384 + cb + 8);
            #pragma unroll
            for (int i = 0; i < 4; i++) {
                u64 xv = pack2(xs[(rb + i) * XS + k]);
                ffma2(acc[i][0], xv, w0a.x);
                ffma2(acc[i][1], xv, w0a.y);
                ffma2(acc[i][2], xv, w1a.x);
                ffma2(acc[i][3], xv, w1a.y);
                ffma2(acc[i][4], xv, w2a.x);
                ffma2(acc[i][5], xv, w2a.y);
            }
            w0a = w0b; w1a = w1b; w2a = w2b;
        }
        #pragma unroll
        for (int i = 0; i < 4; i++) {
            #pragma unroll
            for (int j = 0; j < 6; j++) {
                float lo, hi;
                unpack2(acc[i][j], lo, hi);
                gout[(rb + i) * GS + cb + 2 * j]     = lo + bp[cb + 2 * j];
                gout[(rb + i) * GS + cb + 2 * j + 1] = hi + bp[cb + 2 * j + 1];
            }
        }
        __syncthreads();
    }

    for (int t = tid; t < TN * DD; t += 256) {
        int r = t >> 7, j = t & 127;
        int node = n0 + r;
        if (node >= NN) continue;
        float gir = s_gi[r * GS + j];
        float giz = s_gi[r * GS + 128 + j];
        float gin = s_gi[r * GS + 256 + j];
        float ghr = s_gh[r * GS + j];
        float ghz = s_gh[r * GS + 128 + j];
        float ghn = s_gh[r * GS + 256 + j];
        float h   = s_h[r * XS + j];
        float rr  = sigf(gir + ghr);
        float zz  = sigf(giz + ghz);
        float nn  = tanhf(gin + rr * ghn);
        out[(size_t)node * DD + j] = (1.0f - zz) * nn + zz * h;
    }
}

// ---------------------------------------------------------------------------
extern "C" void kernel_launch(void* const* d_in, const int* in_sizes, int n_in,
                              void* d_out, int out_size) {
    const float* node_feat = (const float*)d_in[0];
    const int*   edge_index = (const int*)d_in[1];
    const float* edge_feat = (const float*)d_in[2];
    const float* W1  = (const float*)d_in[3];
    const float* b1  = (const float*)d_in[4];
    const float* W2  = (const float*)d_in[5];
    const float* b2  = (const float*)d_in[6];
    const float* A1  = (const float*)d_in[7];
    const float* ab1 = (const float*)d_in[8];
    const float* A2  = (const float*)d_in[9];
    const float* ab2 = (const float*)d_in[10];
    const float* Wih = (const float*)d_in[11];
    const float* bih = (const float*)d_in[12];
    const float* Whh = (const float*)d_in[13];
    const float* bhh = (const float*)d_in[14];

    float *msum, *bufA, *bufB;
    cudaGetSymbolAddress((void**)&msum, g_msgsum);
    cudaGetSymbolAddress((void**)&bufA, g_bufA);
    cudaGetSymbolAddress((void**)&bufB, g_bufB);

    const int EDGE_SMEM = (TE * EIS + TE * HS) * (int)sizeof(float);         // 108.5 KB
    const int GRU_SMEM  = (2 * TN * XS + 2 * TN * GS) * (int)sizeof(float);  // 128 KB
    cudaFuncSetAttribute(edge_kernel, cudaFuncAttributeMaxDynamicSharedMemorySize, EDGE_SMEM);
    cudaFuncSetAttribute(gru_kernel,  cudaFuncAttributeMaxDynamicSharedMemorySize, GRU_SMEM);

    const int nElems = NN * DD;

    copy_relu_kernel<<<(nElems + 255) / 256, 256>>>(node_feat, bufA, nElems, 0);

    float* cur = bufA;
    float* nxt = bufB;

    for (int step = 0; step < 4; step++) {
        int ii = step >> 1;

        if (step == 2) {
            copy_relu_kernel<<<(nElems + 255) / 256, 256>>>(cur, cur, nElems, 1);
        }

        cudaMemsetAsync(msum, 0, sizeof(float) * (size_t)nElems);

        edge_kernel<<<MM / TE, 256, EDGE_SMEM>>>(
            cur, edge_index, edge_feat,
            W1 + (size_t)ii * KIN * MSGD,  b1  + (size_t)ii * MSGD,
            W2 + (size_t)ii * MSGD * MSGD, b2  + (size_t)ii * MSGD,
            A1 + (size_t)ii * KIN * MSGD,  ab1 + (size_t)ii * MSGD,
            A2 + (size_t)ii * MSGD * MSGD, ab2 + (size_t)ii * MSGD,
            msum);

        float* outp = (step == 3) ? (float*)d_out : nxt;

        gru_kernel<<<(NN + TN - 1) / TN, 256, GRU_SMEM>>>(
            msum, cur,
            Wih + (size_t)ii * MSGD * 384, bih + (size_t)ii * 384,
            Whh + (size_t)ii * DD * 384,   bhh + (size_t)ii * 384,
            outp);

        if (step < 3) { float* t = cur; cur = nxt; nxt = t; }
    }
}

// round 12
// speedup vs baseline: 1.0074x; 1.0074x over previous
#include <cuda_runtime.h>
#include <math.h>

// Problem constants
#define NN   50000
#define DD   128
#define MM   800000
#define EE   32
#define KIN  160    // D + E
#define MSGD 128

// Edge kernel: 64 edges/block, 128 threads, per-thread 8 rows x 8 cols.
// Transposed smem operands (k-major), row-swizzled to kill bank conflicts.
#define TE   64
#define ETS  66     // s_eiT stride (floats), even -> LDS.64 aligned
#define HTS  66     // s_hT  stride
#define SWZ(k) ((((k) >> 3) & 15) * 2)

// GRU kernel tiling
#define TN   32
#define XS   128
#define GS   384

typedef unsigned long long u64;

// Scratch (allocation-free rule: __device__ globals)
__device__ float g_msgsum[(size_t)NN * DD];
__device__ float g_bufA[(size_t)NN * DD];
__device__ float g_bufB[(size_t)NN * DD];

__device__ __forceinline__ float sigf(float x) { return 1.0f / (1.0f + expf(-x)); }

// ---- packed f32x2 helpers (bit-identical to 2x scalar FFMA) ----
__device__ __forceinline__ u64 pack2(float x) {
    u64 r;
    asm("mov.b64 %0, {%1, %1};" : "=l"(r) : "r"(__float_as_uint(x)));
    return r;
}
__device__ __forceinline__ void ffma2(u64& d, u64 a, u64 b) {
    asm("fma.rn.f32x2 %0, %1, %2, %0;" : "+l"(d) : "l"(a), "l"(b));
}
__device__ __forceinline__ void unpack2(u64 v, float& lo, float& hi) {
    unsigned int a, b;
    asm("mov.b64 {%0, %1}, %2;" : "=r"(a), "=r"(b) : "l"(v));
    lo = __uint_as_float(a); hi = __uint_as_float(b);
}

// ---------------------------------------------------------------------------
__global__ void copy_relu_kernel(const float* __restrict__ src, float* __restrict__ dst,
                                 int n, int do_relu) {
    int i = blockIdx.x * blockDim.x + threadIdx.x;
    if (i < n) {
        float v = src[i];
        dst[i] = do_relu ? fmaxf(v, 0.0f) : v;
    }
}

// ---------------------------------------------------------------------------
// Transposed-A GEMM core: A in smem k-major (rows = k, cols = 64 edges,
// swizzled), W in gmem [k][128]. acc[rowpair][col] packed f32x2.
// A row read = kbeg + k (absolute smem row, drives swizzle); W row = k.
// Both operands double-buffered (software pipeline).
// ---------------------------------------------------------------------------
__device__ __forceinline__ void gemmT(
    const float* __restrict__ As, int ts, int kbeg, int kcnt,
    const float* __restrict__ Wp, int cb, int rb, u64 (&acc)[4][8])
{
    u64 aC[4];
    float4 wC0, wC1;
    {
        int ka = kbeg;
        int s = SWZ(ka);
        #pragma unroll
        for (int rp = 0; rp < 4; rp++)
            aC[rp] = *(const u64*)(As + ka * ts + ((rb + 2 * rp + s) & 63));
        wC0 = *(const float4*)(Wp + cb);
        wC1 = *(const float4*)(Wp + cb + 4);
    }
    #pragma unroll 2
    for (int k = 0; k < kcnt; k++) {
        int kn = (k + 1 < kcnt) ? (k + 1) : 0;
        int ka = kbeg + kn;
        int s = SWZ(ka);
        u64 aN[4];
        #pragma unroll
        for (int rp = 0; rp < 4; rp++)
            aN[rp] = *(const u64*)(As + ka * ts + ((rb + 2 * rp + s) & 63));
        float4 wN0 = *(const float4*)(Wp + kn * MSGD + cb);
        float4 wN1 = *(const float4*)(Wp + kn * MSGD + cb + 4);

        u64 wp[8];
        wp[0] = pack2(wC0.x); wp[1] = pack2(wC0.y);
        wp[2] = pack2(wC0.z); wp[3] = pack2(wC0.w);
        wp[4] = pack2(wC1.x); wp[5] = pack2(wC1.y);
        wp[6] = pack2(wC1.z); wp[7] = pack2(wC1.w);

        #pragma unroll
        for (int rp = 0; rp < 4; rp++)
            #pragma unroll
            for (int c = 0; c < 8; c++)
                ffma2(acc[rp][c], aC[rp], wp[c]);

        #pragma unroll
        for (int rp = 0; rp < 4; rp++) aC[rp] = aN[rp];
        wC0 = wN0; wC1 = wN1;
    }
}

// ---------------------------------------------------------------------------
// Fused edge kernel. 64 edges/block, 128 threads.
// Thread tile: 8 rows (rg = tid>>4, rb = rg*8) x 8 cols (cg = tid&15, cb = cg*8).
// s_eiT [KIN][TE] and s_hT [256][TE] are k-major with row swizzle.
// ---------------------------------------------------------------------------
__global__ void __launch_bounds__(128, 2)
edge_kernel(const float* __restrict__ state,
            const int*   __restrict__ eidx,
            const float* __restrict__ efeat,
            const float* __restrict__ W1p, const float* __restrict__ b1p,
            const float* __restrict__ W2p, const float* __restrict__ b2p,
            const float* __restrict__ A1p, const float* __restrict__ ab1p,
            const float* __restrict__ A2p, const float* __restrict__ ab2p,
            float* __restrict__ msum)
{
    extern __shared__ float sm[];
    float* s_eiT = sm;                  // KIN * ETS
    float* s_hT  = sm + KIN * ETS;      // 256 * HTS
    __shared__ int s_src[TE];
    __shared__ int s_dst[TE];

    const int tid = threadIdx.x;
    const int m0  = blockIdx.x * TE;

    if (tid < TE) {
        s_src[tid] = eidx[m0 + tid];
        s_dst[tid] = eidx[MM + m0 + tid];
    }
    __syncthreads();

    // Gather diff part, transposed: element (k, e) at k*ETS + ((e + SWZ(k)) & 63)
    for (int t = tid; t < TE * 32; t += 128) {
        int e = t >> 5, q = t & 31;
        const float4 a = ((const float4*)(state + (size_t)s_src[e] * DD))[q];
        const float4 b = ((const float4*)(state + (size_t)s_dst[e] * DD))[q];
        float v[4] = { a.x - b.x, a.y - b.y, a.z - b.z, a.w - b.w };
        #pragma unroll
        for (int i = 0; i < 4; i++) {
            int k = q * 4 + i;
            s_eiT[k * ETS + ((e + SWZ(k)) & 63)] = v[i];
        }
    }
    // Edge features, transposed
    for (int t = tid; t < TE * 8; t += 128) {
        int e = t >> 3, q = t & 7;
        float4 v4 = ((const float4*)(efeat + (size_t)(m0 + e) * EE))[q];
        float v[4] = { v4.x, v4.y, v4.z, v4.w };
        #pragma unroll
        for (int i = 0; i < 4; i++) {
            int k = DD + q * 4 + i;
            s_eiT[k * ETS + ((e + SWZ(k)) & 63)] = v[i];
        }
    }
    __syncthreads();

    const int cg = tid & 15;     // 16 col groups x 8 cols
    const int rg = tid >> 4;     // 8 row groups x 8 rows
    const int cb = cg * 8;
    const int rb = rg * 8;

    // ---- GEMM1: H = relu(EI @ W + b); half 0 -> s_hT rows [0,128),
    //      half 1 -> s_hT rows [128,256)
    #pragma unroll
    for (int half = 0; half < 2; half++) {
        const float* Wp = half ? A1p : W1p;
        const float* bp = half ? ab1p : b1p;
        u64 acc[4][8];
        #pragma unroll
        for (int rp = 0; rp < 4; rp++)
            #pragma unroll
            for (int c = 0; c < 8; c++) acc[rp][c] = 0ull;

        gemmT(s_eiT, ETS, 0, KIN, Wp, cb, rb, acc);

        const float4 blo = *(const float4*)(bp + cb);
        const float4 bhi = *(const float4*)(bp + cb + 4);
        const float bb[8] = { blo.x, blo.y, blo.z, blo.w, bhi.x, bhi.y, bhi.z, bhi.w };
        #pragma unroll
        for (int cc = 0; cc < 8; cc++) {
            int krow = half * MSGD + cb + cc;
            int s = SWZ(krow);
            #pragma unroll
            for (int rp = 0; rp < 4; rp++) {
                float lo, hi;
                unpack2(acc[rp][cc], lo, hi);
                float2 st;
                st.x = fmaxf(lo + bb[cc], 0.f);
                st.y = fmaxf(hi + bb[cc], 0.f);
                *(float2*)(s_hT + krow * HTS + ((rb + 2 * rp + s) & 63)) = st;
            }
        }
    }
    __syncthreads();

    // ---- GEMM2a: att = HA @ A2 + ab2 -> sigmoid gates kept in registers ----
    float gl[4][8], gh[4][8];
    {
        u64 acc[4][8];
        #pragma unroll
        for (int rp = 0; rp < 4; rp++)
            #pragma unroll
            for (int c = 0; c < 8; c++) acc[rp][c] = 0ull;

        gemmT(s_hT, HTS, MSGD, MSGD, A2p, cb, rb, acc);

        const float4 alo = *(const float4*)(ab2p + cb);
        const float4 ahi = *(const float4*)(ab2p + cb + 4);
        const float ab[8] = { alo.x, alo.y, alo.z, alo.w, ahi.x, ahi.y, ahi.z, ahi.w };
        #pragma unroll
        for (int rp = 0; rp < 4; rp++)
            #pragma unroll
            for (int cc = 0; cc < 8; cc++) {
                float lo, hi;
                unpack2(acc[rp][cc], lo, hi);
                gl[rp][cc] = sigf(lo + ab[cc]);
                gh[rp][cc] = sigf(hi + ab[cc]);
            }
    }

    // ---- GEMM2b: msg = H1 @ W2 + b2; scatter msg*gate into msum ----
    {
        u64 acc[4][8];
        #pragma unroll
        for (int rp = 0; rp < 4; rp++)
            #pragma unroll
            for (int c = 0; c < 8; c++) acc[rp][c] = 0ull;

        gemmT(s_hT, HTS, 0, MSGD, W2p, cb, rb, acc);

        const float4 blo = *(const float4*)(b2p + cb);
        const float4 bhi = *(const float4*)(b2p + cb + 4);
        const float b2[8] = { blo.x, blo.y, blo.z, blo.w, bhi.x, bhi.y, bhi.z, bhi.w };
        #pragma unroll
        for (int rp = 0; rp < 4; rp++) {
            int r0 = rb + 2 * rp;
            float* d0 = msum + (size_t)s_dst[r0]     * DD + cb;
            float* d1 = msum + (size_t)s_dst[r0 + 1] * DD + cb;
            #pragma unroll
            for (int cc = 0; cc < 8; cc++) {
                float lo, hi;
                unpack2(acc[rp][cc], lo, hi);
                atomicAdd(d0 + cc, (lo + b2[cc]) * gl[rp][cc]);
                atomicAdd(d1 + cc, (hi + b2[cc]) * gh[rp][cc]);
            }
        }
    }
}

// ---------------------------------------------------------------------------
// Fused GRU kernel: per 32-node tile, 256 threads, f32x2 + weight prefetch.
// ---------------------------------------------------------------------------
__global__ void __launch_bounds__(256)
gru_kernel(const float* __restrict__ xmsg, const float* __restrict__ hstate,
           const float* __restrict__ Wih, const float* __restrict__ bih,
           const float* __restrict__ Whh, const float* __restrict__ bhh,
           float* __restrict__ out)
{
    extern __shared__ float sm[];
    float* s_x  = sm;                        // TN * XS
    float* s_h  = s_x + TN * XS;             // TN * XS
    float* s_gi = s_h + TN * XS;             // TN * GS
    float* s_gh = s_gi + TN * GS;            // TN * GS

    const int tid = threadIdx.x;
    const int n0  = blockIdx.x * TN;

    for (int t = tid; t < TN * 32; t += 256) {
        int r = t >> 5, q = t & 31;
        int node = n0 + r;
        float4 vx = make_float4(0.f, 0.f, 0.f, 0.f);
        float4 vh = vx;
        if (node < NN) {
            vx = ((const float4*)(xmsg   + (size_t)node * DD))[q];
            vh = ((const float4*)(hstate + (size_t)node * DD))[q];
        }
        *(float4*)(s_x + r * XS + q * 4) = vx;
        *(float4*)(s_h + r * XS + q * 4) = vh;
    }
    __syncthreads();

    const int lane = tid & 31;
    const int wg   = tid >> 5;
    const int rb   = wg * 4;
    const int cb   = lane * 12;

    #pragma unroll
    for (int pass = 0; pass < 2; pass++) {
        const float* xs = pass ? s_h : s_x;
        const float* Wp = pass ? Whh : Wih;
        const float* bp = pass ? bhh : bih;
        float* gout     = pass ? s_gh : s_gi;

        u64 acc[4][6];
        #pragma unroll
        for (int i = 0; i < 4; i++)
            #pragma unroll
            for (int j = 0; j < 6; j++) acc[i][j] = 0ull;

        ulonglong2 w0a = *(const ulonglong2*)(Wp + 0 * 384 + cb);
        ulonglong2 w1a = *(const ulonglong2*)(Wp + 0 * 384 + cb + 4);
        ulonglong2 w2a = *(const ulonglong2*)(Wp + 0 * 384 + cb + 8);
        for (int k = 0; k < DD; k++) {
            int kn = (k + 1 < DD) ? (k + 1) : 0;
            ulonglong2 w0b = *(const ulonglong2*)(Wp + kn * 384 + cb);
            ulonglong2 w1b = *(const ulonglong2*)(Wp + kn * 384 + cb + 4);
            ulonglong2 w2b = *(const ulonglong2*)(Wp + kn * 384 + cb + 8);
            #pragma unroll
            for (int i = 0; i < 4; i++) {
                u64 xv = pack2(xs[(rb + i) * XS + k]);
                ffma2(acc[i][0], xv, w0a.x);
                ffma2(acc[i][1], xv, w0a.y);
                ffma2(acc[i][2], xv, w1a.x);
                ffma2(acc[i][3], xv, w1a.y);
                ffma2(acc[i][4], xv, w2a.x);
                ffma2(acc[i][5], xv, w2a.y);
            }
            w0a = w0b; w1a = w1b; w2a = w2b;
        }
        #pragma unroll
        for (int i = 0; i < 4; i++) {
            #pragma unroll
            for (int j = 0; j < 6; j++) {
                float lo, hi;
                unpack2(acc[i][j], lo, hi);
                gout[(rb + i) * GS + cb + 2 * j]     = lo + bp[cb + 2 * j];
                gout[(rb + i) * GS + cb + 2 * j + 1] = hi + bp[cb + 2 * j + 1];
            }
        }
        __syncthreads();
    }

    for (int t = tid; t < TN * DD; t += 256) {
        int r = t >> 7, j = t & 127;
        int node = n0 + r;
        if (node >= NN) continue;
        float gir = s_gi[r * GS + j];
        float giz = s_gi[r * GS + 128 + j];
        float gin = s_gi[r * GS + 256 + j];
        float ghr = s_gh[r * GS + j];
        float ghz = s_gh[r * GS + 128 + j];
        float ghn = s_gh[r * GS + 256 + j];
        float h   = s_h[r * XS + j];
        float rr  = sigf(gir + ghr);
        float zz  = sigf(giz + ghz);
        float nn  = tanhf(gin + rr * ghn);
        out[(size_t)node * DD + j] = (1.0f - zz) * nn + zz * h;
    }
}

// ---------------------------------------------------------------------------
extern "C" void kernel_launch(void* const* d_in, const int* in_sizes, int n_in,
                              void* d_out, int out_size) {
    const float* node_feat = (const float*)d_in[0];
    const int*   edge_index = (const int*)d_in[1];
    const float* edge_feat = (const float*)d_in[2];
    const float* W1  = (const float*)d_in[3];
    const float* b1  = (const float*)d_in[4];
    const float* W2  = (const float*)d_in[5];
    const float* b2  = (const float*)d_in[6];
    const float* A1  = (const float*)d_in[7];
    const float* ab1 = (const float*)d_in[8];
    const float* A2  = (const float*)d_in[9];
    const float* ab2 = (const float*)d_in[10];
    const float* Wih = (const float*)d_in[11];
    const float* bih = (const float*)d_in[12];
    const float* Whh = (const float*)d_in[13];
    const float* bhh = (const float*)d_in[14];

    float *msum, *bufA, *bufB;
    cudaGetSymbolAddress((void**)&msum, g_msgsum);
    cudaGetSymbolAddress((void**)&bufA, g_bufA);
    cudaGetSymbolAddress((void**)&bufB, g_bufB);

    const int EDGE_SMEM = (KIN * ETS + 256 * HTS) * (int)sizeof(float);      // ~107 KB
    const int GRU_SMEM  = (2 * TN * XS + 2 * TN * GS) * (int)sizeof(float);  // 128 KB
    cudaFuncSetAttribute(edge_kernel, cudaFuncAttributeMaxDynamicSharedMemorySize, EDGE_SMEM);
    cudaFuncSetAttribute(gru_kernel,  cudaFuncAttributeMaxDynamicSharedMemorySize, GRU_SMEM);

    const int nElems = NN * DD;

    copy_relu_kernel<<<(nElems + 255) / 256, 256>>>(node_feat, bufA, nElems, 0);

    float* cur = bufA;
    float* nxt = bufB;

    for (int step = 0; step < 4; step++) {
        int ii = step >> 1;

        if (step == 2) {
            copy_relu_kernel<<<(nElems + 255) / 256, 256>>>(cur, cur, nElems, 1);
        }

        cudaMemsetAsync(msum, 0, sizeof(float) * (size_t)nElems);

        edge_kernel<<<MM / TE, 128, EDGE_SMEM>>>(
            cur, edge_index, edge_feat,
            W1 + (size_t)ii * KIN * MSGD,  b1  + (size_t)ii * MSGD,
            W2 + (size_t)ii * MSGD * MSGD, b2  + (size_t)ii * MSGD,
            A1 + (size_t)ii * KIN * MSGD,  ab1 + (size_t)ii * MSGD,
            A2 + (size_t)ii * MSGD * MSGD, ab2 + (size_t)ii * MSGD,
            msum);

        float* outp = (step == 3) ? (float*)d_out : nxt;

        gru_kernel<<<(NN + TN - 1) / TN, 256, GRU_SMEM>>>(
            msum, cur,
            Wih + (size_t)ii * MSGD * 384, bih + (size_t)ii * 384,
            Whh + (size_t)ii * DD * 384,   bhh + (size_t)ii * 384,
            outp);

        if (step < 3) { float* t = cur; cur = nxt; nxt = t; }
    }
}

// round 13
// speedup vs baseline: 1.3469x; 1.3370x over previous
#include <cuda_runtime.h>
#include <math.h>

// Problem constants
#define NN   50000
#define DD   128
#define MM   800000
#define EE   32
#define KIN  160    // D + E
#define MSGD 128

// Edge kernel tiling: 64 edges/block, 256 threads, per-thread 8 rows x 4 cols
#define TE   64
#define EIS  164    // padded stride for edge-input tile
#define HS   260    // padded stride for hidden tile

// GRU kernel tiling
#define TN   32
#define XS   128
#define GS   384

typedef unsigned long long u64;

// Scratch (allocation-free rule: __device__ globals)
__device__ float g_msgsum[(size_t)NN * DD];
__device__ float g_bufA[(size_t)NN * DD];
__device__ float g_bufB[(size_t)NN * DD];

__device__ __forceinline__ float sigf(float x) { return 1.0f / (1.0f + expf(-x)); }

// ---- packed f32x2 helpers (bit-identical to 2x scalar FFMA) ----
__device__ __forceinline__ u64 pack2(float x) {
    u64 r;
    asm("mov.b64 %0, {%1, %1};" : "=l"(r) : "r"(__float_as_uint(x)));
    return r;
}
__device__ __forceinline__ void ffma2(u64& d, u64 a, u64 b) {
    asm("fma.rn.f32x2 %0, %1, %2, %0;" : "+l"(d) : "l"(a), "l"(b));
}
__device__ __forceinline__ void unpack2(u64 v, float& lo, float& hi) {
    unsigned int a, b;
    asm("mov.b64 {%0, %1}, %2;" : "=r"(a), "=r"(b) : "l"(v));
    lo = __uint_as_float(a); hi = __uint_as_float(b);
}

// ---------------------------------------------------------------------------
__global__ void copy_relu_kernel(const float* __restrict__ src, float* __restrict__ dst,
                                 int n, int do_relu) {
    int i = blockIdx.x * blockDim.x + threadIdx.x;
    if (i < n) {
        float v = src[i];
        dst[i] = do_relu ? fmaxf(v, 0.0f) : v;
    }
}

// ---------------------------------------------------------------------------
// GEMM core (R8 memory pattern, 8-row tile): A rows from smem via LDS.64
// k-pairs (broadcast), W row via ONE lane-distinct LDG.128 per k (cb=lane*4),
// double-buffered k-pair prefetch. acc[row][2] packed over col pairs.
// ---------------------------------------------------------------------------
__device__ __forceinline__ void gemm8(
    const float* __restrict__ As, int astride, int aoff,
    const float* __restrict__ Wp, int kcnt, int cb, int rb,
    u64 (&acc)[8][2])
{
    ulonglong2 wa = *(const ulonglong2*)(Wp + cb);                 // k0 row
    ulonglong2 wb = *(const ulonglong2*)(Wp + MSGD + cb);          // k0+1 row
    for (int k0 = 0; k0 < kcnt; k0 += 2) {
        int kn = (k0 + 2 < kcnt) ? (k0 + 2) : 0;
        ulonglong2 na = *(const ulonglong2*)(Wp + kn * MSGD + cb);
        ulonglong2 nb = *(const ulonglong2*)(Wp + (kn + 1) * MSGD + cb);
        #pragma unroll
        for (int r = 0; r < 8; r++) {
            float2 a2 = *(const float2*)(As + (rb + r) * astride + aoff + k0);
            u64 p0 = pack2(a2.x);
            u64 p1 = pack2(a2.y);
            ffma2(acc[r][0], p0, wa.x);
            ffma2(acc[r][1], p0, wa.y);
            ffma2(acc[r][0], p1, wb.x);
            ffma2(acc[r][1], p1, wb.y);
        }
        wa = na; wb = nb;
    }
}

// ---------------------------------------------------------------------------
// Fused edge kernel. 64 edges/block, 256 threads.
// Thread tile: 8 rows (rb = warp*8) x 4 cols (cb = lane*4).
// One LDG.128 per warp per k covers the whole 512B weight row (no duplicate
// lanes); edge/hidden operands via broadcast LDS.64 k-pairs.
// 108.5KB smem -> 2 blocks/SM = 16 warps (occ 25%).
// ---------------------------------------------------------------------------
__global__ void __launch_bounds__(256, 2)
edge_kernel(const float* __restrict__ state,
            const int*   __restrict__ eidx,
            const float* __restrict__ efeat,
            const float* __restrict__ W1p, const float* __restrict__ b1p,
            const float* __restrict__ W2p, const float* __restrict__ b2p,
            const float* __restrict__ A1p, const float* __restrict__ ab1p,
            const float* __restrict__ A2p, const float* __restrict__ ab2p,
            float* __restrict__ msum)
{
    extern __shared__ float sm[];
    float* s_ei = sm;              // TE * EIS  (reused as gate buffer later)
    float* s_h  = sm + TE * EIS;   // TE * HS
    __shared__ int s_src[TE];
    __shared__ int s_dst[TE];

    const int tid = threadIdx.x;
    const int m0  = blockIdx.x * TE;

    if (tid < TE) {
        s_src[tid] = eidx[m0 + tid];
        s_dst[tid] = eidx[MM + m0 + tid];
    }
    __syncthreads();

    // Gather diff part: 64 edges x 32 float4
    for (int t = tid; t < TE * 32; t += 256) {
        int e = t >> 5, q = t & 31;
        const float4 a = ((const float4*)(state + (size_t)s_src[e] * DD))[q];
        const float4 b = ((const float4*)(state + (size_t)s_dst[e] * DD))[q];
        float4 v; v.x = a.x - b.x; v.y = a.y - b.y; v.z = a.z - b.z; v.w = a.w - b.w;
        *(float4*)(s_ei + e * EIS + q * 4) = v;
    }
    // Edge features: 64 edges x 8 float4
    for (int t = tid; t < TE * 8; t += 256) {
        int e = t >> 3, q = t & 7;
        float4 v = ((const float4*)(efeat + (size_t)(m0 + e) * EE))[q];
        *(float4*)(s_ei + e * EIS + DD + q * 4) = v;
    }
    __syncthreads();

    const int lane = tid & 31;
    const int warp = tid >> 5;
    const int cb   = lane * 4;   // 32 lanes cover 128 cols, one LDG.128/warp
    const int rb   = warp * 8;   // 8 warps cover 64 rows

    // ---- GEMM1: H = relu(EI @ W + b), halves: 0 = msg net (W1), 1 = att net (A1)
    #pragma unroll
    for (int half = 0; half < 2; half++) {
        const float* Wp = half ? A1p : W1p;
        const float* bp = half ? ab1p : b1p;
        u64 acc[8][2];
        #pragma unroll
        for (int r = 0; r < 8; r++) { acc[r][0] = 0ull; acc[r][1] = 0ull; }

        gemm8(s_ei, EIS, 0, Wp, KIN, cb, rb, acc);

        const float4 bias = *(const float4*)(bp + cb);
        #pragma unroll
        for (int r = 0; r < 8; r++) {
            float v0, v1, v2, v3;
            unpack2(acc[r][0], v0, v1);
            unpack2(acc[r][1], v2, v3);
            float4 o;
            o.x = fmaxf(v0 + bias.x, 0.f);
            o.y = fmaxf(v1 + bias.y, 0.f);
            o.z = fmaxf(v2 + bias.z, 0.f);
            o.w = fmaxf(v3 + bias.w, 0.f);
            *(float4*)(s_h + (rb + r) * HS + half * MSGD + cb) = o;
        }
    }
    __syncthreads();
    // s_ei is dead now; reuse as per-thread gate buffer.

    // ---- GEMM2a: att = HA @ A2 + ab2 -> gate = sigmoid, staged in s_ei ----
    {
        u64 acc[8][2];
        #pragma unroll
        for (int r = 0; r < 8; r++) { acc[r][0] = 0ull; acc[r][1] = 0ull; }

        gemm8(s_h, HS, MSGD, A2p, MSGD, cb, rb, acc);

        const float4 ab = *(const float4*)(ab2p + cb);
        #pragma unroll
        for (int r = 0; r < 8; r++) {
            float a0, a1, a2, a3;
            unpack2(acc[r][0], a0, a1);
            unpack2(acc[r][1], a2, a3);
            float4 g;
            g.x = sigf(a0 + ab.x);
            g.y = sigf(a1 + ab.y);
            g.z = sigf(a2 + ab.z);
            g.w = sigf(a3 + ab.w);
            *(float4*)(s_ei + (rb + r) * EIS + cb) = g;
        }
    }

    // ---- GEMM2b: msg = H1 @ W2 + b2; scatter msg*gate into msum ----
    {
        u64 acc[8][2];
        #pragma unroll
        for (int r = 0; r < 8; r++) { acc[r][0] = 0ull; acc[r][1] = 0ull; }

        gemm8(s_h, HS, 0, W2p, MSGD, cb, rb, acc);

        const float4 b2v = *(const float4*)(b2p + cb);
        #pragma unroll
        for (int r = 0; r < 8; r++) {
            float m0v, m1v, m2v, m3v;
            unpack2(acc[r][0], m0v, m1v);
            unpack2(acc[r][1], m2v, m3v);
            float4 g = *(const float4*)(s_ei + (rb + r) * EIS + cb);
            float* dp = msum + (size_t)s_dst[rb + r] * DD + cb;
            atomicAdd(dp + 0, (m0v + b2v.x) * g.x);
            atomicAdd(dp + 1, (m1v + b2v.y) * g.y);
            atomicAdd(dp + 2, (m2v + b2v.z) * g.z);
            atomicAdd(dp + 3, (m3v + b2v.w) * g.w);
        }
    }
}

// ---------------------------------------------------------------------------
// Fused GRU kernel: per 32-node tile, 256 threads, f32x2 + weight prefetch.
// ---------------------------------------------------------------------------
__global__ void __launch_bounds__(256)
gru_kernel(const float* __restrict__ xmsg, const float* __restrict__ hstate,
           const float* __restrict__ Wih, const float* __restrict__ bih,
           const float* __restrict__ Whh, const float* __restrict__ bhh,
           float* __restrict__ out)
{
    extern __shared__ float sm[];
    float* s_x  = sm;                        // TN * XS
    float* s_h  = s_x + TN * XS;             // TN * XS
    float* s_gi = s_h + TN * XS;             // TN * GS
    float* s_gh = s_gi + TN * GS;            // TN * GS

    const int tid = threadIdx.x;
    const int n0  = blockIdx.x * TN;

    for (int t = tid; t < TN * 32; t += 256) {
        int r = t >> 5, q = t & 31;
        int node = n0 + r;
        float4 vx = make_float4(0.f, 0.f, 0.f, 0.f);
        float4 vh = vx;
        if (node < NN) {
            vx = ((const float4*)(xmsg   + (size_t)node * DD))[q];
            vh = ((const float4*)(hstate + (size_t)node * DD))[q];
        }
        *(float4*)(s_x + r * XS + q * 4) = vx;
        *(float4*)(s_h + r * XS + q * 4) = vh;
    }
    __syncthreads();

    const int lane = tid & 31;
    const int wg   = tid >> 5;
    const int rb   = wg * 4;
    const int cb   = lane * 12;

    #pragma unroll
    for (int pass = 0; pass < 2; pass++) {
        const float* xs = pass ? s_h : s_x;
        const float* Wp = pass ? Whh : Wih;
        const float* bp = pass ? bhh : bih;
        float* gout     = pass ? s_gh : s_gi;

        u64 acc[4][6];
        #pragma unroll
        for (int i = 0; i < 4; i++)
            #pragma unroll
            for (int j = 0; j < 6; j++) acc[i][j] = 0ull;

        ulonglong2 w0a = *(const ulonglong2*)(Wp + 0 * 384 + cb);
        ulonglong2 w1a = *(const ulonglong2*)(Wp + 0 * 384 + cb + 4);
        ulonglong2 w2a = *(const ulonglong2*)(Wp + 0 * 384 + cb + 8);
        for (int k = 0; k < DD; k++) {
            int kn = (k + 1 < DD) ? (k + 1) : 0;
            ulonglong2 w0b = *(const ulonglong2*)(Wp + kn * 384 + cb);
            ulonglong2 w1b = *(const ulonglong2*)(Wp + kn * 384 + cb + 4);
            ulonglong2 w2b = *(const ulonglong2*)(Wp + kn * 384 + cb + 8);
            #pragma unroll
            for (int i = 0; i < 4; i++) {
                u64 xv = pack2(xs[(rb + i) * XS + k]);
                ffma2(acc[i][0], xv, w0a.x);
                ffma2(acc[i][1], xv, w0a.y);
                ffma2(acc[i][2], xv, w1a.x);
                ffma2(acc[i][3], xv, w1a.y);
                ffma2(acc[i][4], xv, w2a.x);
                ffma2(acc[i][5], xv, w2a.y);
            }
            w0a = w0b; w1a = w1b; w2a = w2b;
        }
        #pragma unroll
        for (int i = 0; i < 4; i++) {
            #pragma unroll
            for (int j = 0; j < 6; j++) {
                float lo, hi;
                unpack2(acc[i][j], lo, hi);
                gout[(rb + i) * GS + cb + 2 * j]     = lo + bp[cb + 2 * j];
                gout[(rb + i) * GS + cb + 2 * j + 1] = hi + bp[cb + 2 * j + 1];
            }
        }
        __syncthreads();
    }

    for (int t = tid; t < TN * DD; t += 256) {
        int r = t >> 7, j = t & 127;
        int node = n0 + r;
        if (node >= NN) continue;
        float gir = s_gi[r * GS + j];
        float giz = s_gi[r * GS + 128 + j];
        float gin = s_gi[r * GS + 256 + j];
        float ghr = s_gh[r * GS + j];
        float ghz = s_gh[r * GS + 128 + j];
        float ghn = s_gh[r * GS + 256 + j];
        float h   = s_h[r * XS + j];
        float rr  = sigf(gir + ghr);
        float zz  = sigf(giz + ghz);
        float nn  = tanhf(gin + rr * ghn);
        out[(size_t)node * DD + j] = (1.0f - zz) * nn + zz * h;
    }
}

// ---------------------------------------------------------------------------
extern "C" void kernel_launch(void* const* d_in, const int* in_sizes, int n_in,
                              void* d_out, int out_size) {
    const float* node_feat = (const float*)d_in[0];
    const int*   edge_index = (const int*)d_in[1];
    const float* edge_feat = (const float*)d_in[2];
    const float* W1  = (const float*)d_in[3];
    const float* b1  = (const float*)d_in[4];
    const float* W2  = (const float*)d_in[5];
    const float* b2  = (const float*)d_in[6];
    const float* A1  = (const float*)d_in[7];
    const float* ab1 = (const float*)d_in[8];
    const float* A2  = (const float*)d_in[9];
    const float* ab2 = (const float*)d_in[10];
    const float* Wih = (const float*)d_in[11];
    const float* bih = (const float*)d_in[12];
    const float* Whh = (const float*)d_in[13];
    const float* bhh = (const float*)d_in[14];

    float *msum, *bufA, *bufB;
    cudaGetSymbolAddress((void**)&msum, g_msgsum);
    cudaGetSymbolAddress((void**)&bufA, g_bufA);
    cudaGetSymbolAddress((void**)&bufB, g_bufB);

    const int EDGE_SMEM = (TE * EIS + TE * HS) * (int)sizeof(float);         // 108.5 KB
    const int GRU_SMEM  = (2 * TN * XS + 2 * TN * GS) * (int)sizeof(float);  // 128 KB
    cudaFuncSetAttribute(edge_kernel, cudaFuncAttributeMaxDynamicSharedMemorySize, EDGE_SMEM);
    cudaFuncSetAttribute(gru_kernel,  cudaFuncAttributeMaxDynamicSharedMemorySize, GRU_SMEM);

    const int nElems = NN * DD;

    copy_relu_kernel<<<(nElems + 255) / 256, 256>>>(node_feat, bufA, nElems, 0);

    float* cur = bufA;
    float* nxt = bufB;

    for (int step = 0; step < 4; step++) {
        int ii = step >> 1;

        if (step == 2) {
            copy_relu_kernel<<<(nElems + 255) / 256, 256>>>(cur, cur, nElems, 1);
        }

        cudaMemsetAsync(msum, 0, sizeof(float) * (size_t)nElems);

        edge_kernel<<<MM / TE, 256, EDGE_SMEM>>>(
            cur, edge_index, edge_feat,
            W1 + (size_t)ii * KIN * MSGD,  b1  + (size_t)ii * MSGD,
            W2 + (size_t)ii * MSGD * MSGD, b2  + (size_t)ii * MSGD,
            A1 + (size_t)ii * KIN * MSGD,  ab1 + (size_t)ii * MSGD,
            A2 + (size_t)ii * MSGD * MSGD, ab2 + (size_t)ii * MSGD,
            msum);

        float* outp = (step == 3) ? (float*)d_out : nxt;

        gru_kernel<<<(NN + TN - 1) / TN, 256, GRU_SMEM>>>(
            msum, cur,
            Wih + (size_t)ii * MSGD * 384, bih + (size_t)ii * 384,
            Whh + (size_t)ii * DD * 384,   bhh + (size_t)ii * 384,
            outp);

        if (step < 3) { float* t = cur; cur = nxt; nxt = t; }
    }
}